// round 1
// baseline (speedup 1.0000x reference)
#include <cuda_runtime.h>

// Problem constants
static constexpr int HID  = 64;
static constexpr int OBS  = 20;
static constexpr int PRED = 12;
static constexpr int BMAX = 32768;

static constexpr int TPB = 256;   // threads per block
static constexpr int EPB = 64;    // batch elements per block
static constexpr int UPT = 16;    // hidden units per thread (64 units / 4 unit-groups)
static constexpr int HP  = 68;    // h/x shared-row pad (floats): 272B lane stride -> conflict-free LDS.128
static constexpr int CP  = 65;    // c shared-row pad: (e+u) mod 32 distinct -> conflict-free scalar LDS

// Scratch (allocation-free rule: __device__ globals)
__device__ float g_hs1[(size_t)OBS * BMAX * HID]; // layer0 hidden states, [t][b][k]
__device__ float g_h1[(size_t)BMAX * HID];
__device__ float g_c1[(size_t)BMAX * HID];

__device__ __forceinline__ float sigf(float x) { return 1.0f / (1.0f + __expf(-x)); }

// ---------------------------------------------------------------------------
// Kernel 1: encoder layer 0.  x dim = 2. Writes all hidden states to g_hs1.
// smem: wih[512] whh[16384] bs[256] h[EPB*HP] c[EPB*CP] obs[EPB*40]
// ---------------------------------------------------------------------------
static constexpr int K1_WIH = 0;
static constexpr int K1_WHH = K1_WIH + 512;
static constexpr int K1_BS  = K1_WHH + 256 * 64;
static constexpr int K1_H   = K1_BS + 256;
static constexpr int K1_C   = K1_H + EPB * HP;
static constexpr int K1_OBS = K1_C + EPB * CP;
static constexpr int K1_SMEM = (K1_OBS + EPB * OBS * 2) * 4;

__global__ void __launch_bounds__(TPB, 2) k_layer0(
    const float* __restrict__ obs, const float* __restrict__ wih,
    const float* __restrict__ whh, const float* __restrict__ bih,
    const float* __restrict__ bhh, int B)
{
    extern __shared__ float sm[];
    float* wih_s = sm + K1_WIH;
    float* whh_s = sm + K1_WHH;
    float* bs    = sm + K1_BS;
    float* hsh   = sm + K1_H;
    float* csh   = sm + K1_C;
    float* obs_s = sm + K1_OBS;

    const int tid = threadIdx.x;
    const size_t blockBase = (size_t)blockIdx.x * EPB;

    for (int i = tid; i < 512; i += TPB) wih_s[i] = wih[i];
    for (int i = tid; i < 256 * 64; i += TPB) whh_s[i] = whh[i];
    for (int i = tid; i < 256; i += TPB) bs[i] = bih[i] + bhh[i];
    for (int i = tid; i < EPB * HP; i += TPB) hsh[i] = 0.f;
    for (int i = tid; i < EPB * CP; i += TPB) csh[i] = 0.f;
    for (int i = tid; i < EPB * OBS * 2; i += TPB) {
        int ee = i / (OBS * 2), j = i % (OBS * 2);
        obs_s[ee * (OBS * 2) + j] = obs[(blockBase + ee) * (OBS * 2) + j];
    }

    const int lane = tid & 31, warp = tid >> 5;
    const int e  = ((warp & 1) << 5) | lane;   // local batch element 0..63
    const int ug = warp >> 1;                  // unit group 0..3

    for (int t = 0; t < OBS; ++t) {
        __syncthreads();  // hsh/csh from previous step (or init) complete
        if (t > 0) {      // cooperative, coalesced write of h(t-1) to scratch
            float4* dst = (float4*)(g_hs1 + ((size_t)(t - 1) * B + blockBase) * HID);
            for (int i = tid; i < EPB * HID / 4; i += TPB) {
                int ee = i >> 4, k4 = i & 15;
                dst[i] = *(const float4*)(hsh + ee * HP + k4 * 4);
            }
        }
        float hv[HID];
        #pragma unroll
        for (int k4 = 0; k4 < 16; ++k4) {
            float4 a = *(const float4*)(hsh + e * HP + k4 * 4);
            hv[4 * k4 + 0] = a.x; hv[4 * k4 + 1] = a.y;
            hv[4 * k4 + 2] = a.z; hv[4 * k4 + 3] = a.w;
        }
        const float x0 = obs_s[e * (OBS * 2) + 2 * t];
        const float x1 = obs_s[e * (OBS * 2) + 2 * t + 1];
        __syncthreads();  // all reads of hsh done before overwrite

        #pragma unroll 2
        for (int u = 0; u < UPT; ++u) {
            const int unit = ug * UPT + u;
            float zi = bs[unit]        + wih_s[2 * unit] * x0          + wih_s[2 * unit + 1] * x1;
            float zf = bs[64 + unit]   + wih_s[2 * (64 + unit)] * x0   + wih_s[2 * (64 + unit) + 1] * x1;
            float zg = bs[128 + unit]  + wih_s[2 * (128 + unit)] * x0  + wih_s[2 * (128 + unit) + 1] * x1;
            float zo = bs[192 + unit]  + wih_s[2 * (192 + unit)] * x0  + wih_s[2 * (192 + unit) + 1] * x1;
            const float4* wi4 = (const float4*)(whh_s + unit * 64);
            const float4* wf4 = (const float4*)(whh_s + (64 + unit) * 64);
            const float4* wg4 = (const float4*)(whh_s + (128 + unit) * 64);
            const float4* wo4 = (const float4*)(whh_s + (192 + unit) * 64);
            #pragma unroll
            for (int k = 0; k < 16; ++k) {
                float4 a = wi4[k], b = wf4[k], c4 = wg4[k], d = wo4[k];
                zi += a.x * hv[4*k] + a.y * hv[4*k+1] + a.z * hv[4*k+2] + a.w * hv[4*k+3];
                zf += b.x * hv[4*k] + b.y * hv[4*k+1] + b.z * hv[4*k+2] + b.w * hv[4*k+3];
                zg += c4.x * hv[4*k] + c4.y * hv[4*k+1] + c4.z * hv[4*k+2] + c4.w * hv[4*k+3];
                zo += d.x * hv[4*k] + d.y * hv[4*k+1] + d.z * hv[4*k+2] + d.w * hv[4*k+3];
            }
            float co = csh[e * CP + unit];
            float cn = sigf(zf) * co + sigf(zi) * tanhf(zg);
            float hn = sigf(zo) * tanhf(cn);
            csh[e * CP + unit] = cn;
            hsh[e * HP + unit] = hn;
        }
    }
    __syncthreads();
    {
        float4* dst = (float4*)(g_hs1 + ((size_t)(OBS - 1) * B + blockBase) * HID);
        for (int i = tid; i < EPB * HID / 4; i += TPB) {
            int ee = i >> 4, k4 = i & 15;
            dst[i] = *(const float4*)(hsh + ee * HP + k4 * 4);
        }
    }
}

// ---------------------------------------------------------------------------
// Kernel 2: encoder layer 1. x dim = 64 (hs1). Concatenated [x;h] 128-dot.
// smem: wcat[256*128] bs[256] h[EPB*HP] c[EPB*CP] x[EPB*HP]
// ---------------------------------------------------------------------------
static constexpr int K2_W  = 0;
static constexpr int K2_BS = K2_W + 256 * 128;
static constexpr int K2_H  = K2_BS + 256;
static constexpr int K2_C  = K2_H + EPB * HP;
static constexpr int K2_X  = K2_C + EPB * CP;
static constexpr int K2_SMEM = (K2_X + EPB * HP) * 4;

__global__ void __launch_bounds__(TPB, 1) k_layer1(
    const float* __restrict__ wih, const float* __restrict__ whh,
    const float* __restrict__ bih, const float* __restrict__ bhh, int B)
{
    extern __shared__ float sm[];
    float* wcat = sm + K2_W;
    float* bs   = sm + K2_BS;
    float* hsh  = sm + K2_H;
    float* csh  = sm + K2_C;
    float* xsh  = sm + K2_X;

    const int tid = threadIdx.x;
    const size_t blockBase = (size_t)blockIdx.x * EPB;

    for (int i = tid; i < 256 * 128; i += TPB) {
        int row = i >> 7, col = i & 127;
        wcat[i] = (col < 64) ? wih[row * 64 + col] : whh[row * 64 + (col - 64)];
    }
    for (int i = tid; i < 256; i += TPB) bs[i] = bih[i] + bhh[i];
    for (int i = tid; i < EPB * HP; i += TPB) hsh[i] = 0.f;
    for (int i = tid; i < EPB * CP; i += TPB) csh[i] = 0.f;

    const int lane = tid & 31, warp = tid >> 5;
    const int e  = ((warp & 1) << 5) | lane;
    const int ug = warp >> 1;

    for (int t = 0; t < OBS; ++t) {
        __syncthreads();  // prev-step reads of xsh done; hsh/csh complete
        {   // stage x_t tile (coalesced)
            const float4* src = (const float4*)(g_hs1 + ((size_t)t * B + blockBase) * HID);
            for (int i = tid; i < EPB * HID / 4; i += TPB) {
                int ee = i >> 4, k4 = i & 15;
                *(float4*)(xsh + ee * HP + k4 * 4) = src[i];
            }
        }
        __syncthreads();  // x tile ready
        float v[128];
        #pragma unroll
        for (int k4 = 0; k4 < 16; ++k4) {
            float4 a = *(const float4*)(xsh + e * HP + k4 * 4);
            v[4 * k4 + 0] = a.x; v[4 * k4 + 1] = a.y; v[4 * k4 + 2] = a.z; v[4 * k4 + 3] = a.w;
            float4 b = *(const float4*)(hsh + e * HP + k4 * 4);
            v[64 + 4 * k4 + 0] = b.x; v[64 + 4 * k4 + 1] = b.y;
            v[64 + 4 * k4 + 2] = b.z; v[64 + 4 * k4 + 3] = b.w;
        }
        __syncthreads();  // all reads of hsh done before overwrite

        #pragma unroll 2
        for (int u = 0; u < UPT; ++u) {
            const int unit = ug * UPT + u;
            float zi = bs[unit], zf = bs[64 + unit], zg = bs[128 + unit], zo = bs[192 + unit];
            const float4* wi4 = (const float4*)(wcat + unit * 128);
            const float4* wf4 = (const float4*)(wcat + (64 + unit) * 128);
            const float4* wg4 = (const float4*)(wcat + (128 + unit) * 128);
            const float4* wo4 = (const float4*)(wcat + (192 + unit) * 128);
            #pragma unroll
            for (int k = 0; k < 32; ++k) {
                float4 a = wi4[k], b = wf4[k], c4 = wg4[k], d = wo4[k];
                zi += a.x * v[4*k] + a.y * v[4*k+1] + a.z * v[4*k+2] + a.w * v[4*k+3];
                zf += b.x * v[4*k] + b.y * v[4*k+1] + b.z * v[4*k+2] + b.w * v[4*k+3];
                zg += c4.x * v[4*k] + c4.y * v[4*k+1] + c4.z * v[4*k+2] + c4.w * v[4*k+3];
                zo += d.x * v[4*k] + d.y * v[4*k+1] + d.z * v[4*k+2] + d.w * v[4*k+3];
            }
            float co = csh[e * CP + unit];
            float cn = sigf(zf) * co + sigf(zi) * tanhf(zg);
            float hn = sigf(zo) * tanhf(cn);
            csh[e * CP + unit] = cn;
            hsh[e * HP + unit] = hn;
        }
    }
    __syncthreads();
    for (int i = tid; i < EPB * HID; i += TPB) {
        int ee = i >> 6, k = i & 63;
        g_h1[(blockBase + ee) * HID + k] = hsh[ee * HP + k];
        g_c1[(blockBase + ee) * HID + k] = csh[ee * CP + k];
    }
}

// ---------------------------------------------------------------------------
// Kernel 3: decoder (12 steps, x dim = 2, out-proj fed back).
// smem: wih[512] whh[16384] bs[256] ow[128] ob[4] h[EPB*HP] c[EPB*CP] x[EPB*2]
// ---------------------------------------------------------------------------
static constexpr int K3_WIH = 0;
static constexpr int K3_WHH = K3_WIH + 512;
static constexpr int K3_BS  = K3_WHH + 256 * 64;
static constexpr int K3_OW  = K3_BS + 256;
static constexpr int K3_OB  = K3_OW + 128;
static constexpr int K3_H   = K3_OB + 4;
static constexpr int K3_C   = K3_H + EPB * HP;
static constexpr int K3_X   = K3_C + EPB * CP;
static constexpr int K3_SMEM = (K3_X + EPB * 2) * 4;

__global__ void __launch_bounds__(TPB, 2) k_decoder(
    const float* __restrict__ obs, const float* __restrict__ wih,
    const float* __restrict__ whh, const float* __restrict__ bih,
    const float* __restrict__ bhh, const float* __restrict__ outw,
    const float* __restrict__ outb, float* __restrict__ out, int B)
{
    extern __shared__ float sm[];
    float* wih_s = sm + K3_WIH;
    float* whh_s = sm + K3_WHH;
    float* bs    = sm + K3_BS;
    float* ow    = sm + K3_OW;
    float* ob    = sm + K3_OB;
    float* hsh   = sm + K3_H;
    float* csh   = sm + K3_C;
    float* xsh   = sm + K3_X;

    const int tid = threadIdx.x;
    const size_t blockBase = (size_t)blockIdx.x * EPB;

    for (int i = tid; i < 512; i += TPB) wih_s[i] = wih[i];
    for (int i = tid; i < 256 * 64; i += TPB) whh_s[i] = whh[i];
    for (int i = tid; i < 256; i += TPB) bs[i] = bih[i] + bhh[i];
    for (int i = tid; i < 128; i += TPB) ow[i] = outw[i];
    if (tid < 2) ob[tid] = outb[tid];
    for (int i = tid; i < EPB * HID; i += TPB) {
        int ee = i >> 6, k = i & 63;
        hsh[ee * HP + k] = g_h1[(blockBase + ee) * HID + k];
        csh[ee * CP + k] = g_c1[(blockBase + ee) * HID + k];
    }
    for (int i = tid; i < EPB * 2; i += TPB) {
        int ee = i >> 1, j = i & 1;
        xsh[i] = obs[(blockBase + ee) * (OBS * 2) + (OBS - 1) * 2 + j];
    }

    const int lane = tid & 31, warp = tid >> 5;
    const int e  = ((warp & 1) << 5) | lane;
    const int ug = warp >> 1;

    for (int t = 0; t < PRED; ++t) {
        __syncthreads();  // hsh/csh/xsh ready
        float hv[HID];
        #pragma unroll
        for (int k4 = 0; k4 < 16; ++k4) {
            float4 a = *(const float4*)(hsh + e * HP + k4 * 4);
            hv[4 * k4 + 0] = a.x; hv[4 * k4 + 1] = a.y;
            hv[4 * k4 + 2] = a.z; hv[4 * k4 + 3] = a.w;
        }
        const float x0 = xsh[e * 2], x1 = xsh[e * 2 + 1];
        __syncthreads();  // reads done before overwrite

        #pragma unroll 2
        for (int u = 0; u < UPT; ++u) {
            const int unit = ug * UPT + u;
            float zi = bs[unit]        + wih_s[2 * unit] * x0          + wih_s[2 * unit + 1] * x1;
            float zf = bs[64 + unit]   + wih_s[2 * (64 + unit)] * x0   + wih_s[2 * (64 + unit) + 1] * x1;
            float zg = bs[128 + unit]  + wih_s[2 * (128 + unit)] * x0  + wih_s[2 * (128 + unit) + 1] * x1;
            float zo = bs[192 + unit]  + wih_s[2 * (192 + unit)] * x0  + wih_s[2 * (192 + unit) + 1] * x1;
            const float4* wi4 = (const float4*)(whh_s + unit * 64);
            const float4* wf4 = (const float4*)(whh_s + (64 + unit) * 64);
            const float4* wg4 = (const float4*)(whh_s + (128 + unit) * 64);
            const float4* wo4 = (const float4*)(whh_s + (192 + unit) * 64);
            #pragma unroll
            for (int k = 0; k < 16; ++k) {
                float4 a = wi4[k], b = wf4[k], c4 = wg4[k], d = wo4[k];
                zi += a.x * hv[4*k] + a.y * hv[4*k+1] + a.z * hv[4*k+2] + a.w * hv[4*k+3];
                zf += b.x * hv[4*k] + b.y * hv[4*k+1] + b.z * hv[4*k+2] + b.w * hv[4*k+3];
                zg += c4.x * hv[4*k] + c4.y * hv[4*k+1] + c4.z * hv[4*k+2] + c4.w * hv[4*k+3];
                zo += d.x * hv[4*k] + d.y * hv[4*k+1] + d.z * hv[4*k+2] + d.w * hv[4*k+3];
            }
            float co = csh[e * CP + unit];
            float cn = sigf(zf) * co + sigf(zi) * tanhf(zg);
            float hn = sigf(zo) * tanhf(cn);
            csh[e * CP + unit] = cn;
            hsh[e * HP + unit] = hn;
        }
        __syncthreads();  // full new h in hsh before out-projection
        if (ug == 0) {    // warps 0,1 cover all 64 elems: compute out, feed back
            float o0 = ob[0], o1 = ob[1];
            #pragma unroll
            for (int k4 = 0; k4 < 16; ++k4) {
                float4 hh = *(const float4*)(hsh + e * HP + k4 * 4);
                float4 w0 = *(const float4*)(ow + k4 * 4);
                float4 w1 = *(const float4*)(ow + 64 + k4 * 4);
                o0 += w0.x * hh.x + w0.y * hh.y + w0.z * hh.z + w0.w * hh.w;
                o1 += w1.x * hh.x + w1.y * hh.y + w1.z * hh.z + w1.w * hh.w;
            }
            out[(blockBase + e) * (PRED * 2) + t * 2 + 0] = o0;
            out[(blockBase + e) * (PRED * 2) + t * 2 + 1] = o1;
            xsh[e * 2] = o0;
            xsh[e * 2 + 1] = o1;
        }
    }
}

// ---------------------------------------------------------------------------
extern "C" void kernel_launch(void* const* d_in, const int* in_sizes, int n_in,
                              void* d_out, int out_size)
{
    const float* obs     = (const float*)d_in[0];
    const float* w_ih_l0 = (const float*)d_in[1];
    const float* w_hh_l0 = (const float*)d_in[2];
    const float* b_ih_l0 = (const float*)d_in[3];
    const float* b_hh_l0 = (const float*)d_in[4];
    const float* w_ih_l1 = (const float*)d_in[5];
    const float* w_hh_l1 = (const float*)d_in[6];
    const float* b_ih_l1 = (const float*)d_in[7];
    const float* b_hh_l1 = (const float*)d_in[8];
    const float* dec_w_ih = (const float*)d_in[9];
    const float* dec_w_hh = (const float*)d_in[10];
    const float* dec_b_ih = (const float*)d_in[11];
    const float* dec_b_hh = (const float*)d_in[12];
    const float* out_w   = (const float*)d_in[13];
    const float* out_b   = (const float*)d_in[14];
    float* out = (float*)d_out;

    const int B = in_sizes[0] / (OBS * 2);
    const int grid = B / EPB;

    cudaFuncSetAttribute(k_layer0,  cudaFuncAttributeMaxDynamicSharedMemorySize, K1_SMEM);
    cudaFuncSetAttribute(k_layer1,  cudaFuncAttributeMaxDynamicSharedMemorySize, K2_SMEM);
    cudaFuncSetAttribute(k_decoder, cudaFuncAttributeMaxDynamicSharedMemorySize, K3_SMEM);

    k_layer0<<<grid, TPB, K1_SMEM>>>(obs, w_ih_l0, w_hh_l0, b_ih_l0, b_hh_l0, B);
    k_layer1<<<grid, TPB, K2_SMEM>>>(w_ih_l1, w_hh_l1, b_ih_l1, b_hh_l1, B);
    k_decoder<<<grid, TPB, K3_SMEM>>>(obs, dec_w_ih, dec_w_hh, dec_b_ih, dec_b_hh,
                                      out_w, out_b, out, B);
}

// round 2
// speedup vs baseline: 1.2006x; 1.2006x over previous
#include <cuda_runtime.h>

// Problem constants
static constexpr int HID  = 64;
static constexpr int OBS  = 20;
static constexpr int PRED = 12;
static constexpr int BMAX = 32768;

static constexpr int TPB = 256;   // threads per block
static constexpr int EPB = 64;    // batch elements per block
static constexpr int UPT = 16;    // hidden units per thread
static constexpr int HP  = 68;    // h/x shared-row pad (floats)
static constexpr int CP  = 65;    // c shared-row pad

// Scratch (allocation-free rule: __device__ globals)
__device__ float g_hs1[(size_t)OBS * BMAX * HID];
__device__ float g_h1[(size_t)BMAX * HID];
__device__ float g_c1[(size_t)BMAX * HID];

using u64 = unsigned long long;

// packed dual-FMA: d.lo += a.lo*b.lo ; d.hi += a.hi*b.hi  (SASS FFMA2, PTX-only)
__device__ __forceinline__ void fma2(u64& d, u64 a, u64 b) {
    asm("fma.rn.f32x2 %0, %1, %2, %0;" : "+l"(d) : "l"(a), "l"(b));
}
__device__ __forceinline__ u64 pack0(float x) { return (u64)__float_as_uint(x); }
__device__ __forceinline__ float hsum2(u64 v) {
    return __uint_as_float((unsigned)v) + __uint_as_float((unsigned)(v >> 32));
}
__device__ __forceinline__ float sigf(float x) {
    return __fdividef(1.0f, 1.0f + __expf(-x));
}
__device__ __forceinline__ float tanhf_(float x) {   // 2*sig(2x)-1, rel err ~1e-6
    return fmaf(2.0f, sigf(2.0f * x), -1.0f);
}

// ---------------------------------------------------------------------------
// Kernel 1: encoder layer 0.  x dim = 2. Writes all hidden states to g_hs1.
// ---------------------------------------------------------------------------
static constexpr int K1_WIH = 0;
static constexpr int K1_WHH = K1_WIH + 512;
static constexpr int K1_BS  = K1_WHH + 256 * 64;
static constexpr int K1_H   = K1_BS + 256;
static constexpr int K1_C   = K1_H + EPB * HP;
static constexpr int K1_OBS = K1_C + EPB * CP;
static constexpr int K1_SMEM = (K1_OBS + EPB * OBS * 2) * 4;

__global__ void __launch_bounds__(TPB, 2) k_layer0(
    const float* __restrict__ obs, const float* __restrict__ wih,
    const float* __restrict__ whh, const float* __restrict__ bih,
    const float* __restrict__ bhh, int B)
{
    extern __shared__ float sm[];
    float* wih_s = sm + K1_WIH;
    float* whh_s = sm + K1_WHH;
    float* bs    = sm + K1_BS;
    float* hsh   = sm + K1_H;
    float* csh   = sm + K1_C;
    float* obs_s = sm + K1_OBS;

    const int tid = threadIdx.x;
    const size_t blockBase = (size_t)blockIdx.x * EPB;

    for (int i = tid; i < 512; i += TPB) wih_s[i] = wih[i];
    for (int i = tid; i < 256 * 64; i += TPB) whh_s[i] = whh[i];
    for (int i = tid; i < 256; i += TPB) bs[i] = bih[i] + bhh[i];
    for (int i = tid; i < EPB * HP; i += TPB) hsh[i] = 0.f;
    for (int i = tid; i < EPB * CP; i += TPB) csh[i] = 0.f;
    for (int i = tid; i < EPB * OBS * 2; i += TPB) {
        int ee = i / (OBS * 2), j = i % (OBS * 2);
        obs_s[ee * (OBS * 2) + j] = obs[(blockBase + ee) * (OBS * 2) + j];
    }

    const int lane = tid & 31, warp = tid >> 5;
    const int e  = ((warp & 1) << 5) | lane;
    const int ug = warp >> 1;

    for (int t = 0; t < OBS; ++t) {
        __syncthreads();
        if (t > 0) {
            float4* dst = (float4*)(g_hs1 + ((size_t)(t - 1) * B + blockBase) * HID);
            for (int i = tid; i < EPB * HID / 4; i += TPB) {
                int ee = i >> 4, k4 = i & 15;
                dst[i] = *(const float4*)(hsh + ee * HP + k4 * 4);
            }
        }
        u64 hv[32];
        #pragma unroll
        for (int k4 = 0; k4 < 16; ++k4) {
            ulonglong2 p = *(const ulonglong2*)(hsh + e * HP + k4 * 4);
            hv[2 * k4] = p.x; hv[2 * k4 + 1] = p.y;
        }
        const float x0 = obs_s[e * (OBS * 2) + 2 * t];
        const float x1 = obs_s[e * (OBS * 2) + 2 * t + 1];
        __syncthreads();

        #pragma unroll 2
        for (int u = 0; u < UPT; ++u) {
            const int unit = ug * UPT + u;
            u64 zi = pack0(bs[unit]       + wih_s[2*unit]*x0         + wih_s[2*unit+1]*x1);
            u64 zf = pack0(bs[64 + unit]  + wih_s[2*(64+unit)]*x0    + wih_s[2*(64+unit)+1]*x1);
            u64 zg = pack0(bs[128 + unit] + wih_s[2*(128+unit)]*x0   + wih_s[2*(128+unit)+1]*x1);
            u64 zo = pack0(bs[192 + unit] + wih_s[2*(192+unit)]*x0   + wih_s[2*(192+unit)+1]*x1);
            const ulonglong2* wi2 = (const ulonglong2*)(whh_s + unit * 64);
            const ulonglong2* wf2 = (const ulonglong2*)(whh_s + (64 + unit) * 64);
            const ulonglong2* wg2 = (const ulonglong2*)(whh_s + (128 + unit) * 64);
            const ulonglong2* wo2 = (const ulonglong2*)(whh_s + (192 + unit) * 64);
            #pragma unroll
            for (int k = 0; k < 16; ++k) {
                ulonglong2 a = wi2[k], b = wf2[k], c2 = wg2[k], d = wo2[k];
                fma2(zi, a.x, hv[2*k]); fma2(zi, a.y, hv[2*k+1]);
                fma2(zf, b.x, hv[2*k]); fma2(zf, b.y, hv[2*k+1]);
                fma2(zg, c2.x, hv[2*k]); fma2(zg, c2.y, hv[2*k+1]);
                fma2(zo, d.x, hv[2*k]); fma2(zo, d.y, hv[2*k+1]);
            }
            float co = csh[e * CP + unit];
            float cn = sigf(hsum2(zf)) * co + sigf(hsum2(zi)) * tanhf_(hsum2(zg));
            float hn = sigf(hsum2(zo)) * tanhf_(cn);
            csh[e * CP + unit] = cn;
            hsh[e * HP + unit] = hn;
        }
    }
    __syncthreads();
    {
        float4* dst = (float4*)(g_hs1 + ((size_t)(OBS - 1) * B + blockBase) * HID);
        for (int i = tid; i < EPB * HID / 4; i += TPB) {
            int ee = i >> 4, k4 = i & 15;
            dst[i] = *(const float4*)(hsh + ee * HP + k4 * 4);
        }
    }
}

// ---------------------------------------------------------------------------
// Kernel 2: encoder layer 1. x dim = 64 (hs1). Concatenated [x;h] 128-dot.
// ---------------------------------------------------------------------------
static constexpr int K2_W  = 0;
static constexpr int K2_BS = K2_W + 256 * 128;
static constexpr int K2_H  = K2_BS + 256;
static constexpr int K2_C  = K2_H + EPB * HP;
static constexpr int K2_X  = K2_C + EPB * CP;
static constexpr int K2_SMEM = (K2_X + EPB * HP) * 4;

__global__ void __launch_bounds__(TPB, 1) k_layer1(
    const float* __restrict__ wih, const float* __restrict__ whh,
    const float* __restrict__ bih, const float* __restrict__ bhh, int B)
{
    extern __shared__ float sm[];
    float* wcat = sm + K2_W;
    float* bs   = sm + K2_BS;
    float* hsh  = sm + K2_H;
    float* csh  = sm + K2_C;
    float* xsh  = sm + K2_X;

    const int tid = threadIdx.x;
    const size_t blockBase = (size_t)blockIdx.x * EPB;

    for (int i = tid; i < 256 * 128; i += TPB) {
        int row = i >> 7, col = i & 127;
        wcat[i] = (col < 64) ? wih[row * 64 + col] : whh[row * 64 + (col - 64)];
    }
    for (int i = tid; i < 256; i += TPB) bs[i] = bih[i] + bhh[i];
    for (int i = tid; i < EPB * HP; i += TPB) hsh[i] = 0.f;
    for (int i = tid; i < EPB * CP; i += TPB) csh[i] = 0.f;

    const int lane = tid & 31, warp = tid >> 5;
    const int e  = ((warp & 1) << 5) | lane;
    const int ug = warp >> 5 ? warp >> 1 : warp >> 1;  // keep simple
    const int ug2 = warp >> 1;

    for (int t = 0; t < OBS; ++t) {
        __syncthreads();
        {
            const float4* src = (const float4*)(g_hs1 + ((size_t)t * B + blockBase) * HID);
            for (int i = tid; i < EPB * HID / 4; i += TPB) {
                int ee = i >> 4, k4 = i & 15;
                *(float4*)(xsh + ee * HP + k4 * 4) = src[i];
            }
        }
        __syncthreads();
        u64 v[64];
        #pragma unroll
        for (int k4 = 0; k4 < 16; ++k4) {
            ulonglong2 a = *(const ulonglong2*)(xsh + e * HP + k4 * 4);
            v[2 * k4] = a.x; v[2 * k4 + 1] = a.y;
            ulonglong2 b = *(const ulonglong2*)(hsh + e * HP + k4 * 4);
            v[32 + 2 * k4] = b.x; v[32 + 2 * k4 + 1] = b.y;
        }
        __syncthreads();

        #pragma unroll 2
        for (int u = 0; u < UPT; ++u) {
            const int unit = ug2 * UPT + u;
            u64 zi = pack0(bs[unit]);
            u64 zf = pack0(bs[64 + unit]);
            u64 zg = pack0(bs[128 + unit]);
            u64 zo = pack0(bs[192 + unit]);
            const ulonglong2* wi2 = (const ulonglong2*)(wcat + unit * 128);
            const ulonglong2* wf2 = (const ulonglong2*)(wcat + (64 + unit) * 128);
            const ulonglong2* wg2 = (const ulonglong2*)(wcat + (128 + unit) * 128);
            const ulonglong2* wo2 = (const ulonglong2*)(wcat + (192 + unit) * 128);
            #pragma unroll
            for (int k = 0; k < 32; ++k) {
                ulonglong2 a = wi2[k], b = wf2[k], c2 = wg2[k], d = wo2[k];
                fma2(zi, a.x, v[2*k]); fma2(zi, a.y, v[2*k+1]);
                fma2(zf, b.x, v[2*k]); fma2(zf, b.y, v[2*k+1]);
                fma2(zg, c2.x, v[2*k]); fma2(zg, c2.y, v[2*k+1]);
                fma2(zo, d.x, v[2*k]); fma2(zo, d.y, v[2*k+1]);
            }
            float co = csh[e * CP + unit];
            float cn = sigf(hsum2(zf)) * co + sigf(hsum2(zi)) * tanhf_(hsum2(zg));
            float hn = sigf(hsum2(zo)) * tanhf_(cn);
            csh[e * CP + unit] = cn;
            hsh[e * HP + unit] = hn;
        }
    }
    __syncthreads();
    for (int i = tid; i < EPB * HID; i += TPB) {
        int ee = i >> 6, k = i & 63;
        g_h1[(blockBase + ee) * HID + k] = hsh[ee * HP + k];
        g_c1[(blockBase + ee) * HID + k] = csh[ee * CP + k];
    }
}

// ---------------------------------------------------------------------------
// Kernel 3: decoder (12 steps, x dim = 2, out-proj fed back).
// ---------------------------------------------------------------------------
static constexpr int K3_WIH = 0;
static constexpr int K3_WHH = K3_WIH + 512;
static constexpr int K3_BS  = K3_WHH + 256 * 64;
static constexpr int K3_OW  = K3_BS + 256;
static constexpr int K3_OB  = K3_OW + 128;
static constexpr int K3_H   = K3_OB + 4;
static constexpr int K3_C   = K3_H + EPB * HP;
static constexpr int K3_X   = K3_C + EPB * CP;
static constexpr int K3_SMEM = (K3_X + EPB * 2) * 4;

__global__ void __launch_bounds__(TPB, 2) k_decoder(
    const float* __restrict__ obs, const float* __restrict__ wih,
    const float* __restrict__ whh, const float* __restrict__ bih,
    const float* __restrict__ bhh, const float* __restrict__ outw,
    const float* __restrict__ outb, float* __restrict__ out, int B)
{
    extern __shared__ float sm[];
    float* wih_s = sm + K3_WIH;
    float* whh_s = sm + K3_WHH;
    float* bs    = sm + K3_BS;
    float* ow    = sm + K3_OW;
    float* ob    = sm + K3_OB;
    float* hsh   = sm + K3_H;
    float* csh   = sm + K3_C;
    float* xsh   = sm + K3_X;

    const int tid = threadIdx.x;
    const size_t blockBase = (size_t)blockIdx.x * EPB;

    for (int i = tid; i < 512; i += TPB) wih_s[i] = wih[i];
    for (int i = tid; i < 256 * 64; i += TPB) whh_s[i] = whh[i];
    for (int i = tid; i < 256; i += TPB) bs[i] = bih[i] + bhh[i];
    for (int i = tid; i < 128; i += TPB) ow[i] = outw[i];
    if (tid < 2) ob[tid] = outb[tid];
    for (int i = tid; i < EPB * HID; i += TPB) {
        int ee = i >> 6, k = i & 63;
        hsh[ee * HP + k] = g_h1[(blockBase + ee) * HID + k];
        csh[ee * CP + k] = g_c1[(blockBase + ee) * HID + k];
    }
    for (int i = tid; i < EPB * 2; i += TPB) {
        int ee = i >> 1, j = i & 1;
        xsh[i] = obs[(blockBase + ee) * (OBS * 2) + (OBS - 1) * 2 + j];
    }

    const int lane = tid & 31, warp = tid >> 5;
    const int e  = ((warp & 1) << 5) | lane;
    const int ug = warp >> 1;

    for (int t = 0; t < PRED; ++t) {
        __syncthreads();
        u64 hv[32];
        #pragma unroll
        for (int k4 = 0; k4 < 16; ++k4) {
            ulonglong2 p = *(const ulonglong2*)(hsh + e * HP + k4 * 4);
            hv[2 * k4] = p.x; hv[2 * k4 + 1] = p.y;
        }
        const float x0 = xsh[e * 2], x1 = xsh[e * 2 + 1];
        __syncthreads();

        #pragma unroll 2
        for (int u = 0; u < UPT; ++u) {
            const int unit = ug * UPT + u;
            u64 zi = pack0(bs[unit]       + wih_s[2*unit]*x0         + wih_s[2*unit+1]*x1);
            u64 zf = pack0(bs[64 + unit]  + wih_s[2*(64+unit)]*x0    + wih_s[2*(64+unit)+1]*x1);
            u64 zg = pack0(bs[128 + unit] + wih_s[2*(128+unit)]*x0   + wih_s[2*(128+unit)+1]*x1);
            u64 zo = pack0(bs[192 + unit] + wih_s[2*(192+unit)]*x0   + wih_s[2*(192+unit)+1]*x1);
            const ulonglong2* wi2 = (const ulonglong2*)(whh_s + unit * 64);
            const ulonglong2* wf2 = (const ulonglong2*)(whh_s + (64 + unit) * 64);
            const ulonglong2* wg2 = (const ulonglong2*)(whh_s + (128 + unit) * 64);
            const ulonglong2* wo2 = (const ulonglong2*)(whh_s + (192 + unit) * 64);
            #pragma unroll
            for (int k = 0; k < 16; ++k) {
                ulonglong2 a = wi2[k], b = wf2[k], c2 = wg2[k], d = wo2[k];
                fma2(zi, a.x, hv[2*k]); fma2(zi, a.y, hv[2*k+1]);
                fma2(zf, b.x, hv[2*k]); fma2(zf, b.y, hv[2*k+1]);
                fma2(zg, c2.x, hv[2*k]); fma2(zg, c2.y, hv[2*k+1]);
                fma2(zo, d.x, hv[2*k]); fma2(zo, d.y, hv[2*k+1]);
            }
            float co = csh[e * CP + unit];
            float cn = sigf(hsum2(zf)) * co + sigf(hsum2(zi)) * tanhf_(hsum2(zg));
            float hn = sigf(hsum2(zo)) * tanhf_(cn);
            csh[e * CP + unit] = cn;
            hsh[e * HP + unit] = hn;
        }
        __syncthreads();
        if (ug == 0) {
            float o0 = ob[0], o1 = ob[1];
            #pragma unroll
            for (int k4 = 0; k4 < 16; ++k4) {
                float4 hh = *(const float4*)(hsh + e * HP + k4 * 4);
                float4 w0 = *(const float4*)(ow + k4 * 4);
                float4 w1 = *(const float4*)(ow + 64 + k4 * 4);
                o0 += w0.x * hh.x + w0.y * hh.y + w0.z * hh.z + w0.w * hh.w;
                o1 += w1.x * hh.x + w1.y * hh.y + w1.z * hh.z + w1.w * hh.w;
            }
            out[(blockBase + e) * (PRED * 2) + t * 2 + 0] = o0;
            out[(blockBase + e) * (PRED * 2) + t * 2 + 1] = o1;
            xsh[e * 2] = o0;
            xsh[e * 2 + 1] = o1;
        }
    }
}

// ---------------------------------------------------------------------------
extern "C" void kernel_launch(void* const* d_in, const int* in_sizes, int n_in,
                              void* d_out, int out_size)
{
    const float* obs     = (const float*)d_in[0];
    const float* w_ih_l0 = (const float*)d_in[1];
    const float* w_hh_l0 = (const float*)d_in[2];
    const float* b_ih_l0 = (const float*)d_in[3];
    const float* b_hh_l0 = (const float*)d_in[4];
    const float* w_ih_l1 = (const float*)d_in[5];
    const float* w_hh_l1 = (const float*)d_in[6];
    const float* b_ih_l1 = (const float*)d_in[7];
    const float* b_hh_l1 = (const float*)d_in[8];
    const float* dec_w_ih = (const float*)d_in[9];
    const float* dec_w_hh = (const float*)d_in[10];
    const float* dec_b_ih = (const float*)d_in[11];
    const float* dec_b_hh = (const float*)d_in[12];
    const float* out_w   = (const float*)d_in[13];
    const float* out_b   = (const float*)d_in[14];
    float* out = (float*)d_out;

    const int B = in_sizes[0] / (OBS * 2);
    const int grid = B / EPB;

    cudaFuncSetAttribute(k_layer0,  cudaFuncAttributeMaxDynamicSharedMemorySize, K1_SMEM);
    cudaFuncSetAttribute(k_layer1,  cudaFuncAttributeMaxDynamicSharedMemorySize, K2_SMEM);
    cudaFuncSetAttribute(k_decoder, cudaFuncAttributeMaxDynamicSharedMemorySize, K3_SMEM);

    k_layer0<<<grid, TPB, K1_SMEM>>>(obs, w_ih_l0, w_hh_l0, b_ih_l0, b_hh_l0, B);
    k_layer1<<<grid, TPB, K2_SMEM>>>(w_ih_l1, w_hh_l1, b_ih_l1, b_hh_l1, B);
    k_decoder<<<grid, TPB, K3_SMEM>>>(obs, dec_w_ih, dec_w_hh, dec_b_ih, dec_b_hh,
                                      out_w, out_b, out, B);
}

// round 5
// speedup vs baseline: 1.2633x; 1.0523x over previous
#include <cuda_runtime.h>

// Problem constants
static constexpr int HID  = 64;
static constexpr int OBS  = 20;
static constexpr int PRED = 12;
static constexpr int BMAX = 32768;

static constexpr int TPB = 256;

// Scratch (allocation-free rule: __device__ globals)
__device__ float g_hs1[(size_t)OBS * BMAX * HID];
__device__ float g_h1[(size_t)BMAX * HID];
__device__ float g_c1[(size_t)BMAX * HID];

using u64 = unsigned long long;

__device__ __forceinline__ void fma2(u64& d, u64 a, u64 b) {
    asm("fma.rn.f32x2 %0, %1, %2, %0;" : "+l"(d) : "l"(a), "l"(b));
}
__device__ __forceinline__ u64 pack0(float x) { return (u64)__float_as_uint(x); }
__device__ __forceinline__ float hsum2(u64 v) {
    return __uint_as_float((unsigned)v) + __uint_as_float((unsigned)(v >> 32));
}
__device__ __forceinline__ float sigf(float x) {
    return __fdividef(1.0f, 1.0f + __expf(-x));
}
__device__ __forceinline__ float tanhf_(float x) {
    return fmaf(2.0f, sigf(2.0f * x), -1.0f);
}

// ===========================================================================
// Kernel 1: encoder layer 0.  EPB=128, 2 batch elems per thread (twin scheme).
// c-state stride 65 (>=64 required; odd -> conflict-free).
// ===========================================================================
static constexpr int K1_EPB = 128;
static constexpr int K1_WIH = 0;                          // 512
static constexpr int K1_WHH = 512;                        // 16384
static constexpr int K1_BS  = K1_WHH + 16384;             // 256
static constexpr int K1_H   = K1_BS + 256;                // 128*68
static constexpr int K1_C   = K1_H + K1_EPB * 68;         // 128*65
static constexpr int K1_OBS = K1_C + K1_EPB * 65;         // 128*40
static constexpr int K1_SMEM = (K1_OBS + K1_EPB * OBS * 2) * 4;

__global__ void __launch_bounds__(TPB, 1) k_layer0(
    const float* __restrict__ obs, const float* __restrict__ wih,
    const float* __restrict__ whh, const float* __restrict__ bih,
    const float* __restrict__ bhh, int B)
{
    extern __shared__ float sm[];
    float* wih_s = sm + K1_WIH;
    float* whh_s = sm + K1_WHH;
    float* bs    = sm + K1_BS;
    float* hsh   = sm + K1_H;
    float* csh   = sm + K1_C;
    float* obs_s = sm + K1_OBS;

    const int tid = threadIdx.x;
    const size_t blockBase = (size_t)blockIdx.x * K1_EPB;

    for (int i = tid; i < 512; i += TPB) wih_s[i] = wih[i];
    for (int i = tid; i < 16384; i += TPB) whh_s[i] = whh[i];
    for (int i = tid; i < 256; i += TPB) bs[i] = bih[i] + bhh[i];
    for (int i = tid; i < K1_EPB * 68; i += TPB) hsh[i] = 0.f;
    for (int i = tid; i < K1_EPB * 65; i += TPB) csh[i] = 0.f;
    for (int i = tid; i < K1_EPB * OBS * 2; i += TPB) {
        int ee = i / (OBS * 2), j = i % (OBS * 2);
        obs_s[ee * (OBS * 2) + j] = obs[(blockBase + ee) * (OBS * 2) + j];
    }

    const int lane = tid & 31, warp = tid >> 5;
    const int slot = ((warp & 1) << 5) | lane;
    const int e0 = slot, e1 = slot + 64;
    const int ug = warp >> 1;

    for (int t = 0; t < OBS; ++t) {
        __syncthreads();
        if (t > 0) {
            float4* dst = (float4*)(g_hs1 + ((size_t)(t - 1) * B + blockBase) * HID);
            for (int i = tid; i < K1_EPB * 16; i += TPB) {
                int ee = i >> 4, k4 = i & 15;
                dst[i] = *(const float4*)(hsh + ee * 68 + k4 * 4);
            }
        }
        u64 h0[32], h1[32];
        #pragma unroll
        for (int k4 = 0; k4 < 16; ++k4) {
            ulonglong2 p = *(const ulonglong2*)(hsh + e0 * 68 + k4 * 4);
            h0[2 * k4] = p.x; h0[2 * k4 + 1] = p.y;
            ulonglong2 q = *(const ulonglong2*)(hsh + e1 * 68 + k4 * 4);
            h1[2 * k4] = q.x; h1[2 * k4 + 1] = q.y;
        }
        const float x00 = obs_s[e0 * 40 + 2 * t], x01 = obs_s[e0 * 40 + 2 * t + 1];
        const float x10 = obs_s[e1 * 40 + 2 * t], x11 = obs_s[e1 * 40 + 2 * t + 1];
        __syncthreads();

        #pragma unroll 2
        for (int u = 0; u < 16; ++u) {
            const int unit = ug * 16 + u;
            const float bi = bs[unit], bf = bs[64 + unit], bg = bs[128 + unit], bo = bs[192 + unit];
            const float wi0 = wih_s[2*unit],       wi1 = wih_s[2*unit+1];
            const float wf0 = wih_s[2*(64+unit)],  wf1 = wih_s[2*(64+unit)+1];
            const float wg0 = wih_s[2*(128+unit)], wg1 = wih_s[2*(128+unit)+1];
            const float wo0 = wih_s[2*(192+unit)], wo1 = wih_s[2*(192+unit)+1];
            u64 zi0 = pack0(bi + wi0*x00 + wi1*x01), zi1 = pack0(bi + wi0*x10 + wi1*x11);
            u64 zf0 = pack0(bf + wf0*x00 + wf1*x01), zf1 = pack0(bf + wf0*x10 + wf1*x11);
            u64 zg0 = pack0(bg + wg0*x00 + wg1*x01), zg1 = pack0(bg + wg0*x10 + wg1*x11);
            u64 zo0 = pack0(bo + wo0*x00 + wo1*x01), zo1 = pack0(bo + wo0*x10 + wo1*x11);
            const ulonglong2* wi2 = (const ulonglong2*)(whh_s + unit * 64);
            const ulonglong2* wf2 = (const ulonglong2*)(whh_s + (64 + unit) * 64);
            const ulonglong2* wg2 = (const ulonglong2*)(whh_s + (128 + unit) * 64);
            const ulonglong2* wo2 = (const ulonglong2*)(whh_s + (192 + unit) * 64);
            #pragma unroll
            for (int k = 0; k < 16; ++k) {
                ulonglong2 a = wi2[k], b = wf2[k], c2 = wg2[k], d = wo2[k];
                fma2(zi0, a.x, h0[2*k]); fma2(zi0, a.y, h0[2*k+1]);
                fma2(zi1, a.x, h1[2*k]); fma2(zi1, a.y, h1[2*k+1]);
                fma2(zf0, b.x, h0[2*k]); fma2(zf0, b.y, h0[2*k+1]);
                fma2(zf1, b.x, h1[2*k]); fma2(zf1, b.y, h1[2*k+1]);
                fma2(zg0, c2.x, h0[2*k]); fma2(zg0, c2.y, h0[2*k+1]);
                fma2(zg1, c2.x, h1[2*k]); fma2(zg1, c2.y, h1[2*k+1]);
                fma2(zo0, d.x, h0[2*k]); fma2(zo0, d.y, h0[2*k+1]);
                fma2(zo1, d.x, h1[2*k]); fma2(zo1, d.y, h1[2*k+1]);
            }
            float co0 = csh[e0 * 65 + unit];
            float cn0 = sigf(hsum2(zf0)) * co0 + sigf(hsum2(zi0)) * tanhf_(hsum2(zg0));
            csh[e0 * 65 + unit] = cn0;
            hsh[e0 * 68 + unit] = sigf(hsum2(zo0)) * tanhf_(cn0);
            float co1 = csh[e1 * 65 + unit];
            float cn1 = sigf(hsum2(zf1)) * co1 + sigf(hsum2(zi1)) * tanhf_(hsum2(zg1));
            csh[e1 * 65 + unit] = cn1;
            hsh[e1 * 68 + unit] = sigf(hsum2(zo1)) * tanhf_(cn1);
        }
    }
    __syncthreads();
    {
        float4* dst = (float4*)(g_hs1 + ((size_t)(OBS - 1) * B + blockBase) * HID);
        for (int i = tid; i < K1_EPB * 16; i += TPB) {
            int ee = i >> 4, k4 = i & 15;
            dst[i] = *(const float4*)(hsh + ee * 68 + k4 * 4);
        }
    }
}

// ===========================================================================
// Kernel 2: encoder layer 1 — VERBATIM round-2 version (known passing).
// ===========================================================================
static constexpr int K2_EPB = 64;
static constexpr int K2_W   = 0;                          // 32768
static constexpr int K2_BS  = 32768;                      // 256
static constexpr int K2_H   = K2_BS + 256;                // 64*68
static constexpr int K2_C   = K2_H + K2_EPB * 68;         // 64*65
static constexpr int K2_X   = K2_C + K2_EPB * 65;         // 64*68
static constexpr int K2_SMEM = (K2_X + K2_EPB * 68) * 4;

__global__ void __launch_bounds__(TPB, 1) k_layer1(
    const float* __restrict__ wih, const float* __restrict__ whh,
    const float* __restrict__ bih, const float* __restrict__ bhh, int B)
{
    extern __shared__ float sm[];
    float* wcat = sm + K2_W;
    float* bs   = sm + K2_BS;
    float* hsh  = sm + K2_H;
    float* csh  = sm + K2_C;
    float* xsh  = sm + K2_X;

    const int tid = threadIdx.x;
    const size_t blockBase = (size_t)blockIdx.x * K2_EPB;

    for (int i = tid; i < 256 * 128; i += TPB) {
        int row = i >> 7, col = i & 127;
        wcat[i] = (col < 64) ? wih[row * 64 + col] : whh[row * 64 + (col - 64)];
    }
    for (int i = tid; i < 256; i += TPB) bs[i] = bih[i] + bhh[i];
    for (int i = tid; i < K2_EPB * 68; i += TPB) hsh[i] = 0.f;
    for (int i = tid; i < K2_EPB * 65; i += TPB) csh[i] = 0.f;

    const int lane = tid & 31, warp = tid >> 5;
    const int e  = ((warp & 1) << 5) | lane;
    const int ug = warp >> 1;

    for (int t = 0; t < OBS; ++t) {
        __syncthreads();
        {
            const float4* src = (const float4*)(g_hs1 + ((size_t)t * B + blockBase) * HID);
            for (int i = tid; i < K2_EPB * 16; i += TPB) {
                int ee = i >> 4, k4 = i & 15;
                *(float4*)(xsh + ee * 68 + k4 * 4) = src[i];
            }
        }
        __syncthreads();
        u64 v[64];
        #pragma unroll
        for (int k4 = 0; k4 < 16; ++k4) {
            ulonglong2 a = *(const ulonglong2*)(xsh + e * 68 + k4 * 4);
            v[2 * k4] = a.x; v[2 * k4 + 1] = a.y;
            ulonglong2 b = *(const ulonglong2*)(hsh + e * 68 + k4 * 4);
            v[32 + 2 * k4] = b.x; v[32 + 2 * k4 + 1] = b.y;
        }
        __syncthreads();

        #pragma unroll 2
        for (int u = 0; u < 16; ++u) {
            const int unit = ug * 16 + u;
            u64 zi = pack0(bs[unit]);
            u64 zf = pack0(bs[64 + unit]);
            u64 zg = pack0(bs[128 + unit]);
            u64 zo = pack0(bs[192 + unit]);
            const ulonglong2* wi2 = (const ulonglong2*)(wcat + unit * 128);
            const ulonglong2* wf2 = (const ulonglong2*)(wcat + (64 + unit) * 128);
            const ulonglong2* wg2 = (const ulonglong2*)(wcat + (128 + unit) * 128);
            const ulonglong2* wo2 = (const ulonglong2*)(wcat + (192 + unit) * 128);
            #pragma unroll
            for (int k = 0; k < 32; ++k) {
                ulonglong2 a = wi2[k], b = wf2[k], c2 = wg2[k], d = wo2[k];
                fma2(zi, a.x, v[2*k]); fma2(zi, a.y, v[2*k+1]);
                fma2(zf, b.x, v[2*k]); fma2(zf, b.y, v[2*k+1]);
                fma2(zg, c2.x, v[2*k]); fma2(zg, c2.y, v[2*k+1]);
                fma2(zo, d.x, v[2*k]); fma2(zo, d.y, v[2*k+1]);
            }
            float co = csh[e * 65 + unit];
            float cn = sigf(hsum2(zf)) * co + sigf(hsum2(zi)) * tanhf_(hsum2(zg));
            float hn = sigf(hsum2(zo)) * tanhf_(cn);
            csh[e * 65 + unit] = cn;
            hsh[e * 68 + unit] = hn;
        }
    }
    __syncthreads();
    for (int i = tid; i < K2_EPB * HID; i += TPB) {
        int ee = i >> 6, k = i & 63;
        g_h1[(blockBase + ee) * HID + k] = hsh[ee * 68 + k];
        g_c1[(blockBase + ee) * HID + k] = csh[ee * 65 + k];
    }
}

// ===========================================================================
// Kernel 3: decoder. EPB=128, 2 elems per thread (twin scheme), c stride 65.
// ===========================================================================
static constexpr int K3_EPB = 128;
static constexpr int K3_WIH = 0;
static constexpr int K3_WHH = 512;
static constexpr int K3_BS  = K3_WHH + 16384;
static constexpr int K3_OW  = K3_BS + 256;
static constexpr int K3_OB  = K3_OW + 128;
static constexpr int K3_H   = K3_OB + 4;
static constexpr int K3_C   = K3_H + K3_EPB * 68;
static constexpr int K3_X   = K3_C + K3_EPB * 65;
static constexpr int K3_SMEM = (K3_X + K3_EPB * 2) * 4;

__global__ void __launch_bounds__(TPB, 1) k_decoder(
    const float* __restrict__ obs, const float* __restrict__ wih,
    const float* __restrict__ whh, const float* __restrict__ bih,
    const float* __restrict__ bhh, const float* __restrict__ outw,
    const float* __restrict__ outb, float* __restrict__ out, int B)
{
    extern __shared__ float sm[];
    float* wih_s = sm + K3_WIH;
    float* whh_s = sm + K3_WHH;
    float* bs    = sm + K3_BS;
    float* ow    = sm + K3_OW;
    float* ob    = sm + K3_OB;
    float* hsh   = sm + K3_H;
    float* csh   = sm + K3_C;
    float* xsh   = sm + K3_X;

    const int tid = threadIdx.x;
    const size_t blockBase = (size_t)blockIdx.x * K3_EPB;

    for (int i = tid; i < 512; i += TPB) wih_s[i] = wih[i];
    for (int i = tid; i < 16384; i += TPB) whh_s[i] = whh[i];
    for (int i = tid; i < 256; i += TPB) bs[i] = bih[i] + bhh[i];
    for (int i = tid; i < 128; i += TPB) ow[i] = outw[i];
    if (tid < 2) ob[tid] = outb[tid];
    for (int i = tid; i < K3_EPB * HID; i += TPB) {
        int ee = i >> 6, k = i & 63;
        hsh[ee * 68 + k] = g_h1[(blockBase + ee) * HID + k];
        csh[ee * 65 + k] = g_c1[(blockBase + ee) * HID + k];
    }
    for (int i = tid; i < K3_EPB * 2; i += TPB) {
        int ee = i >> 1, j = i & 1;
        xsh[i] = obs[(blockBase + ee) * (OBS * 2) + (OBS - 1) * 2 + j];
    }

    const int lane = tid & 31, warp = tid >> 5;
    const int slot = ((warp & 1) << 5) | lane;
    const int e0 = slot, e1 = slot + 64;
    const int ug = warp >> 1;

    for (int t = 0; t < PRED; ++t) {
        __syncthreads();
        u64 h0[32], h1[32];
        #pragma unroll
        for (int k4 = 0; k4 < 16; ++k4) {
            ulonglong2 p = *(const ulonglong2*)(hsh + e0 * 68 + k4 * 4);
            h0[2 * k4] = p.x; h0[2 * k4 + 1] = p.y;
            ulonglong2 q = *(const ulonglong2*)(hsh + e1 * 68 + k4 * 4);
            h1[2 * k4] = q.x; h1[2 * k4 + 1] = q.y;
        }
        const float x00 = xsh[e0 * 2], x01 = xsh[e0 * 2 + 1];
        const float x10 = xsh[e1 * 2], x11 = xsh[e1 * 2 + 1];
        __syncthreads();

        #pragma unroll 2
        for (int u = 0; u < 16; ++u) {
            const int unit = ug * 16 + u;
            const float bi = bs[unit], bf = bs[64 + unit], bg = bs[128 + unit], bo = bs[192 + unit];
            const float wi0 = wih_s[2*unit],       wi1 = wih_s[2*unit+1];
            const float wf0 = wih_s[2*(64+unit)],  wf1 = wih_s[2*(64+unit)+1];
            const float wg0 = wih_s[2*(128+unit)], wg1 = wih_s[2*(128+unit)+1];
            const float wo0 = wih_s[2*(192+unit)], wo1 = wih_s[2*(192+unit)+1];
            u64 zi0 = pack0(bi + wi0*x00 + wi1*x01), zi1 = pack0(bi + wi0*x10 + wi1*x11);
            u64 zf0 = pack0(bf + wf0*x00 + wf1*x01), zf1 = pack0(bf + wf0*x10 + wf1*x11);
            u64 zg0 = pack0(bg + wg0*x00 + wg1*x01), zg1 = pack0(bg + wg0*x10 + wg1*x11);
            u64 zo0 = pack0(bo + wo0*x00 + wo1*x01), zo1 = pack0(bo + wo0*x10 + wo1*x11);
            const ulonglong2* wi2 = (const ulonglong2*)(whh_s + unit * 64);
            const ulonglong2* wf2 = (const ulonglong2*)(whh_s + (64 + unit) * 64);
            const ulonglong2* wg2 = (const ulonglong2*)(whh_s + (128 + unit) * 64);
            const ulonglong2* wo2 = (const ulonglong2*)(whh_s + (192 + unit) * 64);
            #pragma unroll
            for (int k = 0; k < 16; ++k) {
                ulonglong2 a = wi2[k], b = wf2[k], c2 = wg2[k], d = wo2[k];
                fma2(zi0, a.x, h0[2*k]); fma2(zi0, a.y, h0[2*k+1]);
                fma2(zi1, a.x, h1[2*k]); fma2(zi1, a.y, h1[2*k+1]);
                fma2(zf0, b.x, h0[2*k]); fma2(zf0, b.y, h0[2*k+1]);
                fma2(zf1, b.x, h1[2*k]); fma2(zf1, b.y, h1[2*k+1]);
                fma2(zg0, c2.x, h0[2*k]); fma2(zg0, c2.y, h0[2*k+1]);
                fma2(zg1, c2.x, h1[2*k]); fma2(zg1, c2.y, h1[2*k+1]);
                fma2(zo0, d.x, h0[2*k]); fma2(zo0, d.y, h0[2*k+1]);
                fma2(zo1, d.x, h1[2*k]); fma2(zo1, d.y, h1[2*k+1]);
            }
            float co0 = csh[e0 * 65 + unit];
            float cn0 = sigf(hsum2(zf0)) * co0 + sigf(hsum2(zi0)) * tanhf_(hsum2(zg0));
            csh[e0 * 65 + unit] = cn0;
            hsh[e0 * 68 + unit] = sigf(hsum2(zo0)) * tanhf_(cn0);
            float co1 = csh[e1 * 65 + unit];
            float cn1 = sigf(hsum2(zf1)) * co1 + sigf(hsum2(zi1)) * tanhf_(hsum2(zg1));
            csh[e1 * 65 + unit] = cn1;
            hsh[e1 * 68 + unit] = sigf(hsum2(zo1)) * tanhf_(cn1);
        }
        __syncthreads();
        if (ug == 0) {
            #pragma unroll
            for (int ei = 0; ei < 2; ++ei) {
                const int e = ei ? e1 : e0;
                float o0 = ob[0], o1 = ob[1];
                #pragma unroll
                for (int k4 = 0; k4 < 16; ++k4) {
                    float4 hh = *(const float4*)(hsh + e * 68 + k4 * 4);
                    float4 w0 = *(const float4*)(ow + k4 * 4);
                    float4 w1 = *(const float4*)(ow + 64 + k4 * 4);
                    o0 += w0.x * hh.x + w0.y * hh.y + w0.z * hh.z + w0.w * hh.w;
                    o1 += w1.x * hh.x + w1.y * hh.y + w1.z * hh.z + w1.w * hh.w;
                }
                out[(blockBase + e) * (PRED * 2) + t * 2 + 0] = o0;
                out[(blockBase + e) * (PRED * 2) + t * 2 + 1] = o1;
                xsh[e * 2] = o0;
                xsh[e * 2 + 1] = o1;
            }
        }
    }
}

// ---------------------------------------------------------------------------
extern "C" void kernel_launch(void* const* d_in, const int* in_sizes, int n_in,
                              void* d_out, int out_size)
{
    const float* obs     = (const float*)d_in[0];
    const float* w_ih_l0 = (const float*)d_in[1];
    const float* w_hh_l0 = (const float*)d_in[2];
    const float* b_ih_l0 = (const float*)d_in[3];
    const float* b_hh_l0 = (const float*)d_in[4];
    const float* w_ih_l1 = (const float*)d_in[5];
    const float* w_hh_l1 = (const float*)d_in[6];
    const float* b_ih_l1 = (const float*)d_in[7];
    const float* b_hh_l1 = (const float*)d_in[8];
    const float* dec_w_ih = (const float*)d_in[9];
    const float* dec_w_hh = (const float*)d_in[10];
    const float* dec_b_ih = (const float*)d_in[11];
    const float* dec_b_hh = (const float*)d_in[12];
    const float* out_w   = (const float*)d_in[13];
    const float* out_b   = (const float*)d_in[14];
    float* out = (float*)d_out;

    const int B = in_sizes[0] / (OBS * 2);

    cudaFuncSetAttribute(k_layer0,  cudaFuncAttributeMaxDynamicSharedMemorySize, K1_SMEM);
    cudaFuncSetAttribute(k_layer1,  cudaFuncAttributeMaxDynamicSharedMemorySize, K2_SMEM);
    cudaFuncSetAttribute(k_decoder, cudaFuncAttributeMaxDynamicSharedMemorySize, K3_SMEM);

    k_layer0<<<B / K1_EPB, TPB, K1_SMEM>>>(obs, w_ih_l0, w_hh_l0, b_ih_l0, b_hh_l0, B);
    k_layer1<<<B / K2_EPB, TPB, K2_SMEM>>>(w_ih_l1, w_hh_l1, b_ih_l1, b_hh_l1, B);
    k_decoder<<<B / K3_EPB, TPB, K3_SMEM>>>(obs, dec_w_ih, dec_w_hh, dec_b_ih, dec_b_hh,
                                            out_w, out_b, out, B);
}